// round 3
// baseline (speedup 1.0000x reference)
#include <cuda_runtime.h>
#include <math.h>
#include <float.h>

// Problem constants
#define B_ROWS   1024
#define EMB_D    512
#define NCLASS   100000
#define CT       128                         // class tile
#define MT       128                         // batch-row tile
#define NTILES   ((NCLASS + CT - 1) / CT)    // 782
#define SCALE_F  30.0f

// ArcFace margin constants (margin = 0.3)
#define COS_M 0.9553364891256061f
#define SIN_M 0.2955202066613396f
#define TH_C  (-0.9553364891256061f)
#define MM_C  0.08865606199840186f

// Scratch (static device globals: allocation-free per harness rules)
__device__ float g_inv_norm[NCLASS];
__device__ float g_m[B_ROWS * NTILES];       // [row][tile] partial max of logits
__device__ float g_s[B_ROWS * NTILES];       // [row][tile] partial sum exp(l - m)
__device__ float g_cos_label[B_ROWS];
__device__ float g_nll[B_ROWS];
__device__ int   g_lab_is64;                 // 1 if labels buffer is int64

// ---------------------------------------------------------------------------
// Kernel A: probe labels dtype. Reads first 512 elements as int64 (4 KB —
// safe even if the buffer is int32/4 KB). If ALL are in [0, NCLASS), the
// buffer is int64; otherwise int32. Deterministic.
// ---------------------------------------------------------------------------
__global__ __launch_bounds__(512) void detect_labels_kernel(const void* __restrict__ labels) {
    __shared__ int bad;
    if (threadIdx.x == 0) bad = 0;
    __syncthreads();
    long long v = ((const long long*)labels)[threadIdx.x];
    if (v < 0 || v >= NCLASS) atomicOr(&bad, 1);
    __syncthreads();
    if (threadIdx.x == 0) g_lab_is64 = bad ? 0 : 1;
}

// ---------------------------------------------------------------------------
// Kernel 0: per-class inverse L2 norm of weight rows. One warp per class.
// ---------------------------------------------------------------------------
__global__ __launch_bounds__(256) void norm_kernel(const float* __restrict__ weight) {
    int gid  = blockIdx.x * blockDim.x + threadIdx.x;
    int wrp  = gid >> 5;
    int lane = gid & 31;
    if (wrp >= NCLASS) return;
    const float* w = weight + (size_t)wrp * EMB_D;
    float s = 0.f;
    #pragma unroll
    for (int k = lane * 4; k < EMB_D; k += 128) {
        float4 v = *(const float4*)&w[k];
        s += v.x * v.x + v.y * v.y + v.z * v.z + v.w * v.w;
    }
    #pragma unroll
    for (int o = 16; o > 0; o >>= 1) s += __shfl_xor_sync(0xffffffffu, s, o);
    if (lane == 0) g_inv_norm[wrp] = rsqrtf(s);
}

// ---------------------------------------------------------------------------
// Kernel 1: tiled GEMM (cosine) + fused online partial logsumexp per row-tile.
// Block: 256 threads, computes MT x CT tile with 8x8 per thread, K chunk 16.
// ---------------------------------------------------------------------------
#define SA 132   // padded smem row stride (floats), keeps 16B alignment

__global__ __launch_bounds__(256) void gemm_lse_kernel(const float* __restrict__ emb,
                                                       const float* __restrict__ weight) {
    __shared__ float As[16 * SA];   // [k][m]
    __shared__ float Bs[16 * SA];   // [k][c]

    const int tid = threadIdx.x;
    const int tx  = tid & 15;       // column group
    const int ty  = tid >> 4;       // row group
    const int c0  = blockIdx.x * CT;
    const int m0  = blockIdx.y * MT;

    float acc[8][8];
    #pragma unroll
    for (int i = 0; i < 8; i++)
        #pragma unroll
        for (int j = 0; j < 8; j++) acc[i][j] = 0.f;

    for (int k0 = 0; k0 < EMB_D; k0 += 16) {
        // Load A tile (128 x 16) and W tile (128 x 16), transposed into smem.
        #pragma unroll
        for (int t = 0; t < 2; t++) {
            int v   = tid + t * 256;       // 0..511 vector id
            int row = v >> 2;
            int kv  = (v & 3) * 4;
            float4 a = *(const float4*)&emb[(size_t)(m0 + row) * EMB_D + k0 + kv];
            As[(kv + 0) * SA + row] = a.x;
            As[(kv + 1) * SA + row] = a.y;
            As[(kv + 2) * SA + row] = a.z;
            As[(kv + 3) * SA + row] = a.w;
            int c = c0 + row;
            float4 b = make_float4(0.f, 0.f, 0.f, 0.f);
            if (c < NCLASS) b = *(const float4*)&weight[(size_t)c * EMB_D + k0 + kv];
            Bs[(kv + 0) * SA + row] = b.x;
            Bs[(kv + 1) * SA + row] = b.y;
            Bs[(kv + 2) * SA + row] = b.z;
            Bs[(kv + 3) * SA + row] = b.w;
        }
        __syncthreads();

        #pragma unroll
        for (int kk = 0; kk < 16; kk++) {
            float4 a0 = *(const float4*)&As[kk * SA + ty * 8];
            float4 a1 = *(const float4*)&As[kk * SA + ty * 8 + 4];
            float4 b0 = *(const float4*)&Bs[kk * SA + tx * 8];
            float4 b1 = *(const float4*)&Bs[kk * SA + tx * 8 + 4];
            float av[8] = {a0.x, a0.y, a0.z, a0.w, a1.x, a1.y, a1.z, a1.w};
            float bv[8] = {b0.x, b0.y, b0.z, b0.w, b1.x, b1.y, b1.z, b1.w};
            #pragma unroll
            for (int i = 0; i < 8; i++)
                #pragma unroll
                for (int j = 0; j < 8; j++) acc[i][j] += av[i] * bv[j];
        }
        __syncthreads();
    }

    // Epilogue: cosine -> logits -> per-row (max, sumexp) over this 128-class tile.
    float inv_n[8];
    #pragma unroll
    for (int j = 0; j < 8; j++) {
        int c = c0 + tx * 8 + j;
        inv_n[j] = (c < NCLASS) ? g_inv_norm[c] : 0.f;
    }

    #pragma unroll
    for (int i = 0; i < 8; i++) {
        float l[8];
        float mx = -FLT_MAX;
        #pragma unroll
        for (int j = 0; j < 8; j++) {
            int c = c0 + tx * 8 + j;
            l[j] = (c < NCLASS) ? SCALE_F * acc[i][j] * inv_n[j] : -FLT_MAX;
            mx = fmaxf(mx, l[j]);
        }
        // reduce max across the 16 column-threads (half-warp segments)
        #pragma unroll
        for (int o = 8; o > 0; o >>= 1)
            mx = fmaxf(mx, __shfl_xor_sync(0xffffffffu, mx, o, 16));
        float sum = 0.f;
        #pragma unroll
        for (int j = 0; j < 8; j++) sum += __expf(l[j] - mx);  // exp(-huge)=0 for invalid
        #pragma unroll
        for (int o = 8; o > 0; o >>= 1)
            sum += __shfl_xor_sync(0xffffffffu, sum, o, 16);
        if (tx == 0) {
            int r = m0 + ty * 8 + i;
            g_m[(size_t)r * NTILES + blockIdx.x] = mx;
            g_s[(size_t)r * NTILES + blockIdx.x] = sum;
        }
    }
}

// ---------------------------------------------------------------------------
// Kernel 2: cosine at the label column, one warp per batch row.
// Labels dtype resolved at runtime via g_lab_is64.
// ---------------------------------------------------------------------------
__global__ __launch_bounds__(256) void label_cos_kernel(const float* __restrict__ emb,
                                                        const void* __restrict__ labels,
                                                        const float* __restrict__ weight) {
    int gid  = blockIdx.x * blockDim.x + threadIdx.x;
    int row  = gid >> 5;
    int lane = gid & 31;
    if (row >= B_ROWS) return;
    long long lab;
    if (g_lab_is64) lab = ((const long long*)labels)[row];
    else            lab = (long long)((const int*)labels)[row];
    // clamp defensively (should never trigger for valid data)
    if (lab < 0) lab = 0;
    if (lab >= NCLASS) lab = NCLASS - 1;
    const float* e = emb + (size_t)row * EMB_D;
    const float* w = weight + (size_t)lab * EMB_D;
    float s = 0.f;
    #pragma unroll
    for (int k = lane * 4; k < EMB_D; k += 128) {
        float4 ev = *(const float4*)&e[k];
        float4 wv = *(const float4*)&w[k];
        s += ev.x * wv.x + ev.y * wv.y + ev.z * wv.z + ev.w * wv.w;
    }
    #pragma unroll
    for (int o = 16; o > 0; o >>= 1) s += __shfl_xor_sync(0xffffffffu, s, o);
    if (lane == 0) g_cos_label[row] = s * g_inv_norm[lab];
}

// ---------------------------------------------------------------------------
// Kernel 3: per-row combine of tile partials + ArcFace label correction.
// ---------------------------------------------------------------------------
__global__ __launch_bounds__(256) void finalize_rows_kernel() {
    const int b   = blockIdx.x;
    const int tid = threadIdx.x;
    __shared__ float sh[256];

    float mx = -FLT_MAX;
    for (int t = tid; t < NTILES; t += 256)
        mx = fmaxf(mx, g_m[(size_t)b * NTILES + t]);
    sh[tid] = mx;
    __syncthreads();
    for (int o = 128; o > 0; o >>= 1) {
        if (tid < o) sh[tid] = fmaxf(sh[tid], sh[tid + o]);
        __syncthreads();
    }
    float M = sh[0];
    __syncthreads();

    float s = 0.f;
    for (int t = tid; t < NTILES; t += 256)
        s += g_s[(size_t)b * NTILES + t] * __expf(g_m[(size_t)b * NTILES + t] - M);
    sh[tid] = s;
    __syncthreads();
    for (int o = 128; o > 0; o >>= 1) {
        if (tid < o) sh[tid] += sh[tid + o];
        __syncthreads();
    }

    if (tid == 0) {
        float S  = sh[0];
        float cv = g_cos_label[b];
        float l_cos = SCALE_F * cv;
        float sine  = sqrtf(fmaxf(0.f, fminf(1.f, 1.f - cv * cv)));
        float phi   = cv * COS_M - sine * SIN_M;
        if (!(cv > TH_C)) phi = cv - MM_C;
        float l_phi = SCALE_F * phi;
        // swap label's plain-cosine term for its phi term in the sum
        float Sc = S - expf(l_cos - M) + expf(l_phi - M);
        g_nll[b] = M + logf(Sc) - l_phi;
    }
}

// ---------------------------------------------------------------------------
// Kernel 4: deterministic mean over rows -> scalar output.
// ---------------------------------------------------------------------------
__global__ __launch_bounds__(256) void mean_kernel(float* __restrict__ out) {
    const int tid = threadIdx.x;
    __shared__ float sh[256];
    float s = 0.f;
    for (int i = tid; i < B_ROWS; i += 256) s += g_nll[i];
    sh[tid] = s;
    __syncthreads();
    for (int o = 128; o > 0; o >>= 1) {
        if (tid < o) sh[tid] += sh[tid + o];
        __syncthreads();
    }
    if (tid == 0) out[0] = sh[0] * (1.0f / (float)B_ROWS);
}

// ---------------------------------------------------------------------------
extern "C" void kernel_launch(void* const* d_in, const int* in_sizes, int n_in,
                              void* d_out, int out_size) {
    const float* emb    = (const float*)d_in[0];
    const void*  labels = d_in[1];
    const float* weight = (const float*)d_in[2];
    float*       out    = (float*)d_out;

    detect_labels_kernel<<<1, 512>>>(labels);
    norm_kernel<<<NCLASS / 8, 256>>>(weight);

    dim3 grid(NTILES, B_ROWS / MT);
    gemm_lse_kernel<<<grid, 256>>>(emb, weight);

    label_cos_kernel<<<B_ROWS / 8, 256>>>(emb, labels, weight);
    finalize_rows_kernel<<<B_ROWS, 256>>>();
    mean_kernel<<<1, 256>>>(out);
}

// round 5
// speedup vs baseline: 2.9885x; 2.9885x over previous
#include <cuda_runtime.h>
#include <math.h>
#include <float.h>
#include <stdint.h>

// ---------------- problem constants ----------------
#define B_ROWS   1024
#define EMB_D    512
#define NCLASS   100000
#define CT       128                              // class tile (N)
#define NTILES   ((NCLASS + CT - 1) / CT)         // 782
#define SCALE_F  30.0f

// ArcFace margin constants (margin = 0.3)
#define COS_M 0.9553364891256061f
#define SIN_M 0.2955202066613396f
#define TH_C  (-0.9553364891256061f)
#define MM_C  0.08865606199840186f

// ---------------- scratch ----------------
__device__ float g_inv_norm[NCLASS];              // 30 / ||w_c||
__device__ float g_m[B_ROWS * NTILES];
__device__ float g_s[B_ROWS * NTILES];
__device__ float g_cos_label[B_ROWS];
__device__ float g_nll[B_ROWS];
__device__ int   g_lab_is64;

// ---------------- helpers ----------------
__device__ __forceinline__ uint32_t smem_u32(const void* p) {
    uint32_t a;
    asm("{ .reg .u64 t; cvta.to.shared.u64 t, %1; cvt.u32.u64 %0, t; }" : "=r"(a) : "l"(p));
    return a;
}
__device__ __forceinline__ void cp16(uint32_t dst, const void* src, int bytes) {
    asm volatile("cp.async.cg.shared.global [%0], [%1], 16, %2;" :: "r"(dst), "l"(src), "r"(bytes));
}
#define CP_COMMIT()  asm volatile("cp.async.commit_group;" ::: "memory")
#define CP_WAIT(n)   asm volatile("cp.async.wait_group %0;" :: "n"(n) : "memory")

__device__ __forceinline__ uint32_t f2tf(float f) {
    uint32_t u;
    asm("cvt.rna.tf32.f32 %0, %1;" : "=r"(u) : "f"(f));
    return u;
}
__device__ __forceinline__ void mma_16_8_8(float* c, const uint32_t* a, uint32_t b0, uint32_t b1) {
    asm volatile(
        "mma.sync.aligned.m16n8k8.row.col.f32.tf32.tf32.f32 "
        "{%0,%1,%2,%3}, {%4,%5,%6,%7}, {%8,%9}, {%0,%1,%2,%3};"
        : "+f"(c[0]), "+f"(c[1]), "+f"(c[2]), "+f"(c[3])
        : "r"(a[0]), "r"(a[1]), "r"(a[2]), "r"(a[3]), "r"(b0), "r"(b1));
}

// smem geometry (floats): padded row stride 36 (144B, 16B aligned, conflict-free frags)
#define RS        36
#define TILE_F    (128 * RS)          // 4608 floats per operand tile
#define STAGE_F   (2 * TILE_F)        // A + B
#define SMEM_F    (2 * STAGE_F + 128 + 512)   // 2 stages + inv_sm + partials
#define SMEM_DYN  (SMEM_F * 4)

// ---------------------------------------------------------------------------
// Kernel A: probe labels dtype (int64 vs int32 under JAX x64-off).
// ---------------------------------------------------------------------------
__global__ __launch_bounds__(512) void detect_labels_kernel(const void* __restrict__ labels) {
    __shared__ int bad;
    if (threadIdx.x == 0) bad = 0;
    __syncthreads();
    long long v = ((const long long*)labels)[threadIdx.x];
    if (v < 0 || v >= NCLASS) atomicOr(&bad, 1);
    __syncthreads();
    if (threadIdx.x == 0) g_lab_is64 = bad ? 0 : 1;
}

// ---------------------------------------------------------------------------
// Kernel 0: per-class 30/||w|| (scale folded).
// ---------------------------------------------------------------------------
__global__ __launch_bounds__(256) void norm_kernel(const float* __restrict__ weight) {
    int gid  = blockIdx.x * blockDim.x + threadIdx.x;
    int wrp  = gid >> 5;
    int lane = gid & 31;
    if (wrp >= NCLASS) return;
    const float* w = weight + (size_t)wrp * EMB_D;
    float s = 0.f;
    #pragma unroll
    for (int k = lane * 4; k < EMB_D; k += 128) {
        float4 v = *(const float4*)&w[k];
        s += v.x * v.x + v.y * v.y + v.z * v.z + v.w * v.w;
    }
    #pragma unroll
    for (int o = 16; o > 0; o >>= 1) s += __shfl_xor_sync(0xffffffffu, s, o);
    if (lane == 0) g_inv_norm[wrp] = SCALE_F * rsqrtf(s);
}

// ---------------------------------------------------------------------------
// Kernel 1: tf32 mma.sync GEMM (128x128x512) + fused per-row logsumexp.
// grid=(NTILES, 8), 256 threads (8 warps: 4 in M x 2 in N), warp tile 32x64.
// ---------------------------------------------------------------------------
__global__ __launch_bounds__(256, 2) void gemm_lse_mma(const float* __restrict__ emb,
                                                       const float* __restrict__ weight) {
    extern __shared__ __align__(16) float sm[];
    float* inv_sm = sm + 2 * STAGE_F;        // 128 floats
    float* sm_pm  = inv_sm + 128;            // [128][2]
    float* sm_ps  = sm_pm + 256;             // [128][2]

    const int tid    = threadIdx.x;
    const int c0     = blockIdx.x * CT;
    const int m_base = blockIdx.y * 128;

    const int wid  = tid >> 5, lane = tid & 31;
    const int wm   = wid & 3;                 // M warp (0..3) -> rows wm*32
    const int wn   = wid >> 2;                // N warp (0..1) -> cols wn*64
    const int g    = lane >> 2, tig = lane & 3;

    if (tid < CT) {
        int c = c0 + tid;
        inv_sm[tid] = (c < NCLASS) ? g_inv_norm[c] : 0.f;
    }

    // ---- async stage loader: K-chunk kt (32 floats) into stage buffer ----
    const uint32_t smem_base = smem_u32(sm);
    auto load_stage = [&](int kt, int stage) {
        const int k0 = kt * 32;
        const uint32_t sa = smem_base + stage * (STAGE_F * 4);
        const uint32_t sb = sa + TILE_F * 4;
        #pragma unroll
        for (int i = 0; i < 4; i++) {
            int id = tid + i * 256;            // 0..1023
            int r  = id >> 3;
            int u  = id & 7;
            // A: embeddings rows
            cp16(sa + (r * RS) * 4 + u * 16,
                 emb + (size_t)(m_base + r) * EMB_D + k0 + u * 4, 16);
            // B: class rows (zero-fill out of range)
            int c  = c0 + r;
            int cc = (c < NCLASS) ? c : (NCLASS - 1);
            cp16(sb + (r * RS) * 4 + u * 16,
                 weight + (size_t)cc * EMB_D + k0 + u * 4,
                 (c < NCLASS) ? 16 : 0);
        }
        CP_COMMIT();
    };

    float acc[2][8][4];
    #pragma unroll
    for (int mi = 0; mi < 2; mi++)
        #pragma unroll
        for (int ni = 0; ni < 8; ni++)
            #pragma unroll
            for (int q = 0; q < 4; q++) acc[mi][ni][q] = 0.f;

    load_stage(0, 0);
    load_stage(1, 1);

    #pragma unroll 1
    for (int kt = 0; kt < 16; kt++) {
        if (kt == 15) { CP_WAIT(0); } else { CP_WAIT(1); }
        __syncthreads();

        const int stage = kt & 1;
        const float* As = sm + stage * STAGE_F;
        const float* Bs = As + TILE_F;

        #pragma unroll
        for (int ks = 0; ks < 4; ks++) {
            const int kk = ks * 8;
            uint32_t a[2][4];
            #pragma unroll
            for (int mi = 0; mi < 2; mi++) {
                const float* ab = As + (wm * 32 + mi * 16 + g) * RS + kk + tig;
                a[mi][0] = f2tf(ab[0]);
                a[mi][1] = f2tf(ab[8 * RS]);
                a[mi][2] = f2tf(ab[4]);
                a[mi][3] = f2tf(ab[8 * RS + 4]);
            }
            #pragma unroll
            for (int ni = 0; ni < 8; ni++) {
                const float* bb = Bs + (wn * 64 + ni * 8 + g) * RS + kk + tig;
                uint32_t b0 = f2tf(bb[0]);
                uint32_t b1 = f2tf(bb[4]);
                mma_16_8_8(acc[0][ni], a[0], b0, b1);
                mma_16_8_8(acc[1][ni], a[1], b0, b1);
            }
        }
        __syncthreads();
        if (kt + 2 < 16) load_stage(kt + 2, stage);
    }

    // ---- epilogue: per-row (max, sumexp) over this 128-class tile ----
    #pragma unroll
    for (int mi = 0; mi < 2; mi++) {
        #pragma unroll
        for (int half = 0; half < 2; half++) {
            const int row = wm * 32 + mi * 16 + half * 8 + g;   // block-local row
            float lv[16];
            float mx = -FLT_MAX;
            #pragma unroll
            for (int ni = 0; ni < 8; ni++) {
                int col = wn * 64 + ni * 8 + 2 * tig;
                float v0 = acc[mi][ni][half * 2 + 0] * inv_sm[col];
                float v1 = acc[mi][ni][half * 2 + 1] * inv_sm[col + 1];
                if (c0 + col     >= NCLASS) v0 = -FLT_MAX;
                if (c0 + col + 1 >= NCLASS) v1 = -FLT_MAX;
                lv[ni * 2]     = v0;
                lv[ni * 2 + 1] = v1;
                mx = fmaxf(mx, fmaxf(v0, v1));
            }
            float ss = 0.f;
            #pragma unroll
            for (int j = 0; j < 16; j++) ss += __expf(lv[j] - mx);
            // quad reduce (lanes share g, differ in tig): xor 1, xor 2
            #pragma unroll
            for (int d = 1; d <= 2; d <<= 1) {
                float om = __shfl_xor_sync(0xffffffffu, mx, d);
                float os = __shfl_xor_sync(0xffffffffu, ss, d);
                float nm = fmaxf(mx, om);
                ss = ss * __expf(mx - nm) + os * __expf(om - nm);
                mx = nm;
            }
            if (tig == 0) {
                sm_pm[row * 2 + wn] = mx;
                sm_ps[row * 2 + wn] = ss;
            }
        }
    }
    __syncthreads();

    if (tid < 128) {
        float m0 = sm_pm[tid * 2], m1 = sm_pm[tid * 2 + 1];
        float s0 = sm_ps[tid * 2], s1 = sm_ps[tid * 2 + 1];
        float M = fmaxf(m0, m1);
        float S = s0 * __expf(m0 - M) + s1 * __expf(m1 - M);
        g_m[(size_t)(m_base + tid) * NTILES + blockIdx.x] = M;
        g_s[(size_t)(m_base + tid) * NTILES + blockIdx.x] = S;
    }
}

// ---------------------------------------------------------------------------
// Kernel 2: cosine at the label column (fp32 exact), one warp per row.
// ---------------------------------------------------------------------------
__global__ __launch_bounds__(256) void label_cos_kernel(const float* __restrict__ emb,
                                                        const void* __restrict__ labels,
                                                        const float* __restrict__ weight) {
    int gid  = blockIdx.x * blockDim.x + threadIdx.x;
    int row  = gid >> 5;
    int lane = gid & 31;
    if (row >= B_ROWS) return;
    long long lab;
    if (g_lab_is64) lab = ((const long long*)labels)[row];
    else            lab = (long long)((const int*)labels)[row];
    if (lab < 0) lab = 0;
    if (lab >= NCLASS) lab = NCLASS - 1;
    const float* e = emb + (size_t)row * EMB_D;
    const float* w = weight + (size_t)lab * EMB_D;
    float s = 0.f;
    #pragma unroll
    for (int k = lane * 4; k < EMB_D; k += 128) {
        float4 ev = *(const float4*)&e[k];
        float4 wv = *(const float4*)&w[k];
        s += ev.x * wv.x + ev.y * wv.y + ev.z * wv.z + ev.w * wv.w;
    }
    #pragma unroll
    for (int o = 16; o > 0; o >>= 1) s += __shfl_xor_sync(0xffffffffu, s, o);
    if (lane == 0) g_cos_label[row] = s * g_inv_norm[lab] * (1.0f / SCALE_F);
}

// ---------------------------------------------------------------------------
// Kernel 3: combine tile partials + ArcFace label correction.
// ---------------------------------------------------------------------------
__global__ __launch_bounds__(256) void finalize_rows_kernel() {
    const int b   = blockIdx.x;
    const int tid = threadIdx.x;
    __shared__ float sh[256];

    float mx = -FLT_MAX;
    for (int t = tid; t < NTILES; t += 256)
        mx = fmaxf(mx, g_m[(size_t)b * NTILES + t]);
    sh[tid] = mx;
    __syncthreads();
    for (int o = 128; o > 0; o >>= 1) {
        if (tid < o) sh[tid] = fmaxf(sh[tid], sh[tid + o]);
        __syncthreads();
    }
    float M = sh[0];
    __syncthreads();

    float s = 0.f;
    for (int t = tid; t < NTILES; t += 256)
        s += g_s[(size_t)b * NTILES + t] * __expf(g_m[(size_t)b * NTILES + t] - M);
    sh[tid] = s;
    __syncthreads();
    for (int o = 128; o > 0; o >>= 1) {
        if (tid < o) sh[tid] += sh[tid + o];
        __syncthreads();
    }

    if (tid == 0) {
        float S  = sh[0];
        float cv = g_cos_label[b];
        float l_cos = SCALE_F * cv;
        float sine  = sqrtf(fmaxf(0.f, fminf(1.f, 1.f - cv * cv)));
        float phi   = cv * COS_M - sine * SIN_M;
        if (!(cv > TH_C)) phi = cv - MM_C;
        float l_phi = SCALE_F * phi;
        float Sc = S - expf(l_cos - M) + expf(l_phi - M);
        g_nll[b] = M + logf(Sc) - l_phi;
    }
}

// ---------------------------------------------------------------------------
// Kernel 4: mean -> scalar.
// ---------------------------------------------------------------------------
__global__ __launch_bounds__(256) void mean_kernel(float* __restrict__ out) {
    const int tid = threadIdx.x;
    __shared__ float sh[256];
    float s = 0.f;
    for (int i = tid; i < B_ROWS; i += 256) s += g_nll[i];
    sh[tid] = s;
    __syncthreads();
    for (int o = 128; o > 0; o >>= 1) {
        if (tid < o) sh[tid] += sh[tid + o];
        __syncthreads();
    }
    if (tid == 0) out[0] = sh[0] * (1.0f / (float)B_ROWS);
}

// ---------------------------------------------------------------------------
extern "C" void kernel_launch(void* const* d_in, const int* in_sizes, int n_in,
                              void* d_out, int out_size) {
    const float* emb    = (const float*)d_in[0];
    const void*  labels = d_in[1];
    const float* weight = (const float*)d_in[2];
    float*       out    = (float*)d_out;

    cudaFuncSetAttribute(gemm_lse_mma, cudaFuncAttributeMaxDynamicSharedMemorySize, SMEM_DYN);

    detect_labels_kernel<<<1, 512>>>(labels);
    norm_kernel<<<NCLASS / 8, 256>>>(weight);

    dim3 grid(NTILES, B_ROWS / 128);
    gemm_lse_mma<<<grid, 256, SMEM_DYN>>>(emb, weight);

    label_cos_kernel<<<B_ROWS / 8, 256>>>(emb, labels, weight);
    finalize_rows_kernel<<<B_ROWS, 256>>>();
    mean_kernel<<<1, 256>>>(out);
}

// round 7
// speedup vs baseline: 5.7618x; 1.9280x over previous
#include <cuda_runtime.h>
#include <cuda_fp16.h>
#include <math.h>
#include <float.h>
#include <stdint.h>

// ---------------- problem constants ----------------
#define B_ROWS   1024
#define EMB_D    512
#define NCLASS   100000
#define CT       128                              // class tile (N)
#define NTILES   ((NCLASS + CT - 1) / CT)         // 782
#define MBLK     8                                // B_ROWS / 128
#define SCALE_F  30.0f

// ArcFace margin constants (margin = 0.3)
#define COS_M 0.9553364891256061f
#define SIN_M 0.2955202066613396f
#define TH_C  (-0.9553364891256061f)
#define MM_C  0.08865606199840186f

// ---------------- scratch ----------------
__device__ __half g_wh[(size_t)NCLASS * EMB_D];   // fp16 weight with 30/||w|| folded
__device__ __half g_eh[B_ROWS * EMB_D];           // fp16 embeddings
__device__ float  g_inv_norm[NCLASS];             // 30 / ||w_c|| (for exact label path)
__device__ float  g_m[B_ROWS * NTILES];
__device__ float  g_s[B_ROWS * NTILES];
__device__ float  g_cos_label[B_ROWS];
__device__ float  g_nll[B_ROWS];
__device__ int    g_lab_is64;

// ---------------- helpers ----------------
__device__ __forceinline__ uint32_t smem_u32(const void* p) {
    uint32_t a;
    asm("{ .reg .u64 t; cvta.to.shared.u64 t, %1; cvt.u32.u64 %0, t; }" : "=r"(a) : "l"(p));
    return a;
}
__device__ __forceinline__ void cp16(uint32_t dst, const void* src, int bytes) {
    asm volatile("cp.async.cg.shared.global [%0], [%1], 16, %2;" :: "r"(dst), "l"(src), "r"(bytes));
}
#define CP_COMMIT()  asm volatile("cp.async.commit_group;" ::: "memory")
#define CP_WAIT(n)   asm volatile("cp.async.wait_group %0;" :: "n"(n) : "memory")

__device__ __forceinline__ void mma_16816(float* c, const uint32_t* a, uint32_t b0, uint32_t b1) {
    asm volatile(
        "mma.sync.aligned.m16n8k16.row.col.f32.f16.f16.f32 "
        "{%0,%1,%2,%3}, {%4,%5,%6,%7}, {%8,%9}, {%0,%1,%2,%3};"
        : "+f"(c[0]), "+f"(c[1]), "+f"(c[2]), "+f"(c[3])
        : "r"(a[0]), "r"(a[1]), "r"(a[2]), "r"(a[3]), "r"(b0), "r"(b1));
}

// smem geometry: fp16, K-chunk 64, padded row stride 72 halves (144 B)
#define RS_H        72
#define TILE_H      (128 * RS_H)                   // halves per operand tile
#define STAGE_B     (2 * TILE_H * 2)               // bytes per stage (A + B)
#define SMEM_DYN    (2 * STAGE_B + 2048)           // 2 stages + partials

// ---------------------------------------------------------------------------
// Kernel A: probe labels dtype (int64 vs int32 under JAX x64-off).
// ---------------------------------------------------------------------------
__global__ __launch_bounds__(512) void detect_labels_kernel(const void* __restrict__ labels) {
    __shared__ int bad;
    if (threadIdx.x == 0) bad = 0;
    __syncthreads();
    long long v = ((const long long*)labels)[threadIdx.x];
    if (v < 0 || v >= NCLASS) atomicOr(&bad, 1);
    __syncthreads();
    if (threadIdx.x == 0) g_lab_is64 = bad ? 0 : 1;
}

// ---------------------------------------------------------------------------
// Kernel 0: fused per-class norm + fp16 convert (scale 30/||w|| folded).
// ---------------------------------------------------------------------------
__global__ __launch_bounds__(256) void norm_convert_w(const float* __restrict__ weight) {
    int gid  = blockIdx.x * blockDim.x + threadIdx.x;
    int c    = gid >> 5;
    int lane = gid & 31;
    if (c >= NCLASS) return;
    const float* w = weight + (size_t)c * EMB_D;
    float4 v[4];
    float s = 0.f;
    #pragma unroll
    for (int i = 0; i < 4; i++) {
        v[i] = *(const float4*)&w[lane * 4 + i * 128];
        s += v[i].x * v[i].x + v[i].y * v[i].y + v[i].z * v[i].z + v[i].w * v[i].w;
    }
    #pragma unroll
    for (int o = 16; o > 0; o >>= 1) s += __shfl_xor_sync(0xffffffffu, s, o);
    float sc = SCALE_F * rsqrtf(s);
    if (lane == 0) g_inv_norm[c] = sc;
    __half* dst = g_wh + (size_t)c * EMB_D;
    #pragma unroll
    for (int i = 0; i < 4; i++) {
        __half2 h0 = __floats2half2_rn(v[i].x * sc, v[i].y * sc);
        __half2 h1 = __floats2half2_rn(v[i].z * sc, v[i].w * sc);
        *(uint2*)&dst[lane * 4 + i * 128] = make_uint2(*(uint32_t*)&h0, *(uint32_t*)&h1);
    }
}

// ---------------------------------------------------------------------------
// Kernel 0b: embeddings fp32 -> fp16.
// ---------------------------------------------------------------------------
__global__ __launch_bounds__(256) void convert_e(const float* __restrict__ emb) {
    int i = blockIdx.x * blockDim.x + threadIdx.x;     // one float4 per thread
    float4 v = *(const float4*)&emb[i * 4];
    __half2 h0 = __floats2half2_rn(v.x, v.y);
    __half2 h1 = __floats2half2_rn(v.z, v.w);
    *(uint2*)&g_eh[i * 4] = make_uint2(*(uint32_t*)&h0, *(uint32_t*)&h1);
}

// ---------------------------------------------------------------------------
// Kernel 1: fp16 mma.sync m16n8k16 GEMM (128x128x512) + fused logsumexp.
// grid = (MBLK, NTILES); 256 threads: 8 warps = 4(M) x 2(N), warp tile 32x64.
// ---------------------------------------------------------------------------
__global__ __launch_bounds__(256, 2) void gemm_lse_h(void) {
    extern __shared__ __align__(16) char smc[];
    __half* sm    = (__half*)smc;
    float*  sm_pm = (float*)(smc + 2 * STAGE_B);       // [128][2]
    float*  sm_ps = sm_pm + 256;

    const int tid    = threadIdx.x;
    const int m_base = blockIdx.x * 128;
    const int c0     = blockIdx.y * CT;

    const int wid  = tid >> 5, lane = tid & 31;
    const int wm   = wid & 3;
    const int wn   = wid >> 2;
    const int g    = lane >> 2, tig = lane & 3;

    const uint32_t smem_base = smem_u32(sm);
    // FULL coverage: 256 rows x 8 x 16B units = 2048 cp16 per stage.
    auto load_stage = [&](int kt, int stage) {
        const int k0 = kt * 64;
        const uint32_t sa = smem_base + stage * STAGE_B;
        const uint32_t sb = sa + TILE_H * 2;
        #pragma unroll
        for (int i = 0; i < 8; i++) {
            int id = tid + i * 256;              // 0..2047
            int r  = id >> 3;                    // 0..255
            int u  = id & 7;                     // 16B unit (8 halves), 0..7
            if (r < 128) {
                cp16(sa + (r * RS_H + u * 8) * 2,
                     g_eh + (size_t)(m_base + r) * EMB_D + k0 + u * 8, 16);
            } else {
                int rr = r - 128;
                int c  = c0 + rr;
                int cc = (c < NCLASS) ? c : (NCLASS - 1);
                cp16(sb + (rr * RS_H + u * 8) * 2,
                     g_wh + (size_t)cc * EMB_D + k0 + u * 8,
                     (c < NCLASS) ? 16 : 0);
            }
        }
        CP_COMMIT();
    };

    float acc[2][8][4];
    #pragma unroll
    for (int mi = 0; mi < 2; mi++)
        #pragma unroll
        for (int ni = 0; ni < 8; ni++)
            #pragma unroll
            for (int q = 0; q < 4; q++) acc[mi][ni][q] = 0.f;

    load_stage(0, 0);
    load_stage(1, 1);

    #pragma unroll 1
    for (int kt = 0; kt < 8; kt++) {
        if (kt == 7) { CP_WAIT(0); } else { CP_WAIT(1); }
        __syncthreads();

        const int stage = kt & 1;
        const __half* As = sm + stage * (STAGE_B / 2);
        const __half* Bs = As + TILE_H;

        #pragma unroll
        for (int ks = 0; ks < 4; ks++) {
            const int kk = ks * 16;
            uint32_t a[2][4];
            #pragma unroll
            for (int mi = 0; mi < 2; mi++) {
                const __half* ab = As + (wm * 32 + mi * 16 + g) * RS_H + kk + 2 * tig;
                a[mi][0] = *(const uint32_t*)(ab);
                a[mi][1] = *(const uint32_t*)(ab + 8 * RS_H);
                a[mi][2] = *(const uint32_t*)(ab + 8);
                a[mi][3] = *(const uint32_t*)(ab + 8 * RS_H + 8);
            }
            #pragma unroll
            for (int ni = 0; ni < 8; ni++) {
                const __half* bb = Bs + (wn * 64 + ni * 8 + g) * RS_H + kk + 2 * tig;
                uint32_t b0 = *(const uint32_t*)(bb);
                uint32_t b1 = *(const uint32_t*)(bb + 8);
                mma_16816(acc[0][ni], a[0], b0, b1);
                mma_16816(acc[1][ni], a[1], b0, b1);
            }
        }
        __syncthreads();
        if (kt + 2 < 8) load_stage(kt + 2, stage);
    }

    // ---- epilogue: per-row (max, sumexp); scale already folded into weights.
    #pragma unroll
    for (int mi = 0; mi < 2; mi++) {
        #pragma unroll
        for (int half = 0; half < 2; half++) {
            const int row = wm * 32 + mi * 16 + half * 8 + g;
            float lv[16];
            float mx = -FLT_MAX;
            #pragma unroll
            for (int ni = 0; ni < 8; ni++) {
                int col = wn * 64 + ni * 8 + 2 * tig;
                float v0 = acc[mi][ni][half * 2 + 0];
                float v1 = acc[mi][ni][half * 2 + 1];
                if (c0 + col     >= NCLASS) v0 = -FLT_MAX;
                if (c0 + col + 1 >= NCLASS) v1 = -FLT_MAX;
                lv[ni * 2]     = v0;
                lv[ni * 2 + 1] = v1;
                mx = fmaxf(mx, fmaxf(v0, v1));
            }
            float ss = 0.f;
            #pragma unroll
            for (int j = 0; j < 16; j++) ss += __expf(lv[j] - mx);
            #pragma unroll
            for (int d = 1; d <= 2; d <<= 1) {
                float om = __shfl_xor_sync(0xffffffffu, mx, d);
                float os = __shfl_xor_sync(0xffffffffu, ss, d);
                float nm = fmaxf(mx, om);
                ss = ss * __expf(mx - nm) + os * __expf(om - nm);
                mx = nm;
            }
            if (tig == 0) {
                sm_pm[row * 2 + wn] = mx;
                sm_ps[row * 2 + wn] = ss;
            }
        }
    }
    __syncthreads();

    if (tid < 128) {
        float m0 = sm_pm[tid * 2], m1 = sm_pm[tid * 2 + 1];
        float s0 = sm_ps[tid * 2], s1 = sm_ps[tid * 2 + 1];
        float M = fmaxf(m0, m1);
        float S = s0 * __expf(m0 - M) + s1 * __expf(m1 - M);
        g_m[(size_t)(m_base + tid) * NTILES + blockIdx.y] = M;
        g_s[(size_t)(m_base + tid) * NTILES + blockIdx.y] = S;
    }
}

// ---------------------------------------------------------------------------
// Kernel 2: exact fp32 cosine at the label column, one warp per row.
// ---------------------------------------------------------------------------
__global__ __launch_bounds__(256) void label_cos_kernel(const float* __restrict__ emb,
                                                        const void* __restrict__ labels,
                                                        const float* __restrict__ weight) {
    int gid  = blockIdx.x * blockDim.x + threadIdx.x;
    int row  = gid >> 5;
    int lane = gid & 31;
    if (row >= B_ROWS) return;
    long long lab;
    if (g_lab_is64) lab = ((const long long*)labels)[row];
    else            lab = (long long)((const int*)labels)[row];
    if (lab < 0) lab = 0;
    if (lab >= NCLASS) lab = NCLASS - 1;
    const float* e = emb + (size_t)row * EMB_D;
    const float* w = weight + (size_t)lab * EMB_D;
    float s = 0.f;
    #pragma unroll
    for (int k = lane * 4; k < EMB_D; k += 128) {
        float4 ev = *(const float4*)&e[k];
        float4 wv = *(const float4*)&w[k];
        s += ev.x * wv.x + ev.y * wv.y + ev.z * wv.z + ev.w * wv.w;
    }
    #pragma unroll
    for (int o = 16; o > 0; o >>= 1) s += __shfl_xor_sync(0xffffffffu, s, o);
    if (lane == 0) g_cos_label[row] = s * g_inv_norm[lab] * (1.0f / SCALE_F);
}

// ---------------------------------------------------------------------------
// Kernel 3: combine tile partials + ArcFace label correction.
// ---------------------------------------------------------------------------
__global__ __launch_bounds__(256) void finalize_rows_kernel() {
    const int b   = blockIdx.x;
    const int tid = threadIdx.x;
    __shared__ float sh[256];

    float mx = -FLT_MAX;
    for (int t = tid; t < NTILES; t += 256)
        mx = fmaxf(mx, g_m[(size_t)b * NTILES + t]);
    sh[tid] = mx;
    __syncthreads();
    for (int o = 128; o > 0; o >>= 1) {
        if (tid < o) sh[tid] = fmaxf(sh[tid], sh[tid + o]);
        __syncthreads();
    }
    float M = sh[0];
    __syncthreads();

    float s = 0.f;
    for (int t = tid; t < NTILES; t += 256)
        s += g_s[(size_t)b * NTILES + t] * __expf(g_m[(size_t)b * NTILES + t] - M);
    sh[tid] = s;
    __syncthreads();
    for (int o = 128; o > 0; o >>= 1) {
        if (tid < o) sh[tid] += sh[tid + o];
        __syncthreads();
    }

    if (tid == 0) {
        float S  = sh[0];
        float cv = g_cos_label[b];
        float l_cos = SCALE_F * cv;
        float sine  = sqrtf(fmaxf(0.f, fminf(1.f, 1.f - cv * cv)));
        float phi   = cv * COS_M - sine * SIN_M;
        if (!(cv > TH_C)) phi = cv - MM_C;
        float l_phi = SCALE_F * phi;
        float Sc = S - expf(l_cos - M) + expf(l_phi - M);
        g_nll[b] = M + logf(Sc) - l_phi;
    }
}

// ---------------------------------------------------------------------------
// Kernel 4: mean -> scalar.
// ---------------------------------------------------------------------------
__global__ __launch_bounds__(256) void mean_kernel(float* __restrict__ out) {
    const int tid = threadIdx.x;
    __shared__ float sh[256];
    float s = 0.f;
    for (int i = tid; i < B_ROWS; i += 256) s += g_nll[i];
    sh[tid] = s;
    __syncthreads();
    for (int o = 128; o > 0; o >>= 1) {
        if (tid < o) sh[tid] += sh[tid + o];
        __syncthreads();
    }
    if (tid == 0) out[0] = sh[0] * (1.0f / (float)B_ROWS);
}

// ---------------------------------------------------------------------------
extern "C" void kernel_launch(void* const* d_in, const int* in_sizes, int n_in,
                              void* d_out, int out_size) {
    const float* emb    = (const float*)d_in[0];
    const void*  labels = d_in[1];
    const float* weight = (const float*)d_in[2];
    float*       out    = (float*)d_out;

    cudaFuncSetAttribute(gemm_lse_h, cudaFuncAttributeMaxDynamicSharedMemorySize, SMEM_DYN);

    detect_labels_kernel<<<1, 512>>>(labels);
    norm_convert_w<<<(NCLASS + 7) / 8, 256>>>(weight);
    convert_e<<<B_ROWS * EMB_D / 4 / 256, 256>>>(emb);

    dim3 grid(MBLK, NTILES);
    gemm_lse_h<<<grid, 256, SMEM_DYN>>>();

    label_cos_kernel<<<B_ROWS / 8, 256>>>(emb, labels, weight);
    finalize_rows_kernel<<<B_ROWS, 256>>>();
    mean_kernel<<<1, 256>>>(out);
}

// round 8
// speedup vs baseline: 6.2574x; 1.0860x over previous
#include <cuda_runtime.h>
#include <cuda_fp16.h>
#include <math.h>
#include <float.h>
#include <stdint.h>

// ---------------- problem constants ----------------
#define B_ROWS   1024
#define EMB_D    512
#define NCLASS   100000
#define CT       128                              // class tile (N)
#define NTILES   ((NCLASS + CT - 1) / CT)         // 782
#define MBLK     8                                // B_ROWS / 128
#define SCALE_F  30.0f

// ArcFace margin constants (margin = 0.3)
#define COS_M 0.9553364891256061f
#define SIN_M 0.2955202066613396f
#define TH_C  (-0.9553364891256061f)
#define MM_C  0.08865606199840186f

// ---------------- scratch ----------------
__device__ __half g_wh[(size_t)NCLASS * EMB_D];   // fp16 weight with 30/||w|| folded
__device__ __half g_eh[B_ROWS * EMB_D];           // fp16 embeddings
__device__ float  g_inv_norm[NCLASS];             // 30 / ||w_c|| (exact label path)
__device__ float  g_m[B_ROWS * NTILES];
__device__ float  g_s[B_ROWS * NTILES];
__device__ float  g_cos_label[B_ROWS];
__device__ float  g_nll[B_ROWS];
__device__ int    g_lab_is64;

// ---------------- helpers ----------------
__device__ __forceinline__ uint32_t smem_u32(const void* p) {
    uint32_t a;
    asm("{ .reg .u64 t; cvta.to.shared.u64 t, %1; cvt.u32.u64 %0, t; }" : "=r"(a) : "l"(p));
    return a;
}
__device__ __forceinline__ void cp16(uint32_t dst, const void* src, int bytes) {
    asm volatile("cp.async.cg.shared.global [%0], [%1], 16, %2;" :: "r"(dst), "l"(src), "r"(bytes));
}
#define CP_COMMIT()  asm volatile("cp.async.commit_group;" ::: "memory")
#define CP_WAIT(n)   asm volatile("cp.async.wait_group %0;" :: "n"(n) : "memory")

__device__ __forceinline__ void mma_16816(float* c, const uint32_t* a, uint32_t b0, uint32_t b1) {
    asm volatile(
        "mma.sync.aligned.m16n8k16.row.col.f32.f16.f16.f32 "
        "{%0,%1,%2,%3}, {%4,%5,%6,%7}, {%8,%9}, {%0,%1,%2,%3};"
        : "+f"(c[0]), "+f"(c[1]), "+f"(c[2]), "+f"(c[3])
        : "r"(a[0]), "r"(a[1]), "r"(a[2]), "r"(a[3]), "r"(b0), "r"(b1));
}
__device__ __forceinline__ void ldm_x4(uint32_t* r, uint32_t addr) {
    asm volatile("ldmatrix.sync.aligned.m8n8.x4.shared.b16 {%0,%1,%2,%3}, [%4];"
                 : "=r"(r[0]), "=r"(r[1]), "=r"(r[2]), "=r"(r[3]) : "r"(addr));
}

// smem geometry: fp16, K-chunk 64, padded row stride 72 halves (144 B)
#define RS_H        72
#define TILE_H      (128 * RS_H)                   // halves per operand tile
#define STAGE_B     (2 * TILE_H * 2)               // bytes per stage (A + B)
#define SMEM_DYN    (2 * STAGE_B + 2048)           // 2 stages + partials

// ---------------------------------------------------------------------------
// Kernel A: probe labels dtype (int64 vs int32 under JAX x64-off).
// ---------------------------------------------------------------------------
__global__ __launch_bounds__(512) void detect_labels_kernel(const void* __restrict__ labels) {
    __shared__ int bad;
    if (threadIdx.x == 0) bad = 0;
    __syncthreads();
    long long v = ((const long long*)labels)[threadIdx.x];
    if (v < 0 || v >= NCLASS) atomicOr(&bad, 1);
    __syncthreads();
    if (threadIdx.x == 0) g_lab_is64 = bad ? 0 : 1;
}

// ---------------------------------------------------------------------------
// Kernel 0: fused per-class norm + fp16 convert (scale 30/||w|| folded).
// ---------------------------------------------------------------------------
__global__ __launch_bounds__(256) void norm_convert_w(const float* __restrict__ weight) {
    int gid  = blockIdx.x * blockDim.x + threadIdx.x;
    int c    = gid >> 5;
    int lane = gid & 31;
    if (c >= NCLASS) return;
    const float* w = weight + (size_t)c * EMB_D;
    float4 v[4];
    float s = 0.f;
    #pragma unroll
    for (int i = 0; i < 4; i++) {
        v[i] = *(const float4*)&w[lane * 4 + i * 128];
        s += v[i].x * v[i].x + v[i].y * v[i].y + v[i].z * v[i].z + v[i].w * v[i].w;
    }
    #pragma unroll
    for (int o = 16; o > 0; o >>= 1) s += __shfl_xor_sync(0xffffffffu, s, o);
    float sc = SCALE_F * rsqrtf(s);
    if (lane == 0) g_inv_norm[c] = sc;
    __half* dst = g_wh + (size_t)c * EMB_D;
    #pragma unroll
    for (int i = 0; i < 4; i++) {
        __half2 h0 = __floats2half2_rn(v[i].x * sc, v[i].y * sc);
        __half2 h1 = __floats2half2_rn(v[i].z * sc, v[i].w * sc);
        *(uint2*)&dst[lane * 4 + i * 128] = make_uint2(*(uint32_t*)&h0, *(uint32_t*)&h1);
    }
}

// ---------------------------------------------------------------------------
// Kernel 0b: embeddings fp32 -> fp16.
// ---------------------------------------------------------------------------
__global__ __launch_bounds__(256) void convert_e(const float* __restrict__ emb) {
    int i = blockIdx.x * blockDim.x + threadIdx.x;     // one float4 per thread
    float4 v = *(const float4*)&emb[i * 4];
    __half2 h0 = __floats2half2_rn(v.x, v.y);
    __half2 h1 = __floats2half2_rn(v.z, v.w);
    *(uint2*)&g_eh[i * 4] = make_uint2(*(uint32_t*)&h0, *(uint32_t*)&h1);
}

// ---------------------------------------------------------------------------
// Kernel 1: fp16 mma.sync m16n8k16 GEMM (128x128x512) + fused logsumexp.
// grid = (MBLK, NTILES); 256 threads: 8 warps = 4(M) x 2(N), warp tile 32x64.
// Fragment loads via ldmatrix.x4 (conflict-free with 144B row stride).
// ---------------------------------------------------------------------------
__global__ __launch_bounds__(256, 2) void gemm_lse_h(void) {
    extern __shared__ __align__(16) char smc[];
    __half* sm    = (__half*)smc;
    float*  sm_pm = (float*)(smc + 2 * STAGE_B);       // [128][2]
    float*  sm_ps = sm_pm + 256;

    const int tid    = threadIdx.x;
    const int m_base = blockIdx.x * 128;
    const int c0     = blockIdx.y * CT;

    const int wid  = tid >> 5, lane = tid & 31;
    const int wm   = wid & 3;
    const int wn   = wid >> 2;
    const int g    = lane >> 2, tig = lane & 3;

    const uint32_t smem_base = smem_u32(sm);

    // ldmatrix per-lane byte offsets (within a stage):
    // A x4: regs {a0,a1,a2,a3} = {(mLo,kLo),(mHi,kLo),(mLo,kHi),(mHi,kHi)}
    const uint32_t a_off = ((uint32_t)(wm * 32 + (lane & 7) + ((lane >> 3) & 1) * 8) * RS_H
                            + ((lane >> 4) & 1) * 8) * 2;
    // B x4: regs {b0(ni),b1(ni),b0(ni+1),b1(ni+1)}
    const uint32_t b_off = (uint32_t)TILE_H * 2
                         + ((uint32_t)(wn * 64 + (lane & 7) + ((lane >> 4) & 1) * 8) * RS_H
                            + ((lane >> 3) & 1) * 8) * 2;

    // FULL coverage: 256 rows x 8 x 16B units = 2048 cp16 per stage.
    auto load_stage = [&](int kt, int stage) {
        const int k0 = kt * 64;
        const uint32_t sa = smem_base + stage * STAGE_B;
        const uint32_t sb = sa + TILE_H * 2;
        #pragma unroll
        for (int i = 0; i < 8; i++) {
            int id = tid + i * 256;              // 0..2047
            int r  = id >> 3;                    // 0..255
            int u  = id & 7;                     // 16B unit (8 halves)
            if (r < 128) {
                cp16(sa + (r * RS_H + u * 8) * 2,
                     g_eh + (size_t)(m_base + r) * EMB_D + k0 + u * 8, 16);
            } else {
                int rr = r - 128;
                int c  = c0 + rr;
                int cc = (c < NCLASS) ? c : (NCLASS - 1);
                cp16(sb + (rr * RS_H + u * 8) * 2,
                     g_wh + (size_t)cc * EMB_D + k0 + u * 8,
                     (c < NCLASS) ? 16 : 0);
            }
        }
        CP_COMMIT();
    };

    float acc[2][8][4];
    #pragma unroll
    for (int mi = 0; mi < 2; mi++)
        #pragma unroll
        for (int ni = 0; ni < 8; ni++)
            #pragma unroll
            for (int q = 0; q < 4; q++) acc[mi][ni][q] = 0.f;

    load_stage(0, 0);
    load_stage(1, 1);

    #pragma unroll 1
    for (int kt = 0; kt < 8; kt++) {
        if (kt == 7) { CP_WAIT(0); } else { CP_WAIT(1); }
        __syncthreads();

        const int stage = kt & 1;
        const uint32_t sA = smem_base + stage * STAGE_B + a_off;
        const uint32_t sB = smem_base + stage * STAGE_B + b_off;

        #pragma unroll
        for (int ks = 0; ks < 4; ks++) {
            const uint32_t kb = (uint32_t)(ks * 16) * 2;   // byte offset of kk
            uint32_t a[2][4];
            ldm_x4(a[0], sA + kb);
            ldm_x4(a[1], sA + (16 * RS_H) * 2 + kb);
            #pragma unroll
            for (int nip = 0; nip < 4; nip++) {
                uint32_t br[4];
                ldm_x4(br, sB + (uint32_t)(nip * 16 * RS_H) * 2 + kb);
                mma_16816(acc[0][2 * nip],     a[0], br[0], br[1]);
                mma_16816(acc[1][2 * nip],     a[1], br[0], br[1]);
                mma_16816(acc[0][2 * nip + 1], a[0], br[2], br[3]);
                mma_16816(acc[1][2 * nip + 1], a[1], br[2], br[3]);
            }
        }
        __syncthreads();
        if (kt + 2 < 8) load_stage(kt + 2, stage);
    }

    // ---- epilogue: per-row (max, sumexp); scale already folded into weights.
    #pragma unroll
    for (int mi = 0; mi < 2; mi++) {
        #pragma unroll
        for (int half = 0; half < 2; half++) {
            const int row = wm * 32 + mi * 16 + half * 8 + g;
            float lv[16];
            float mx = -FLT_MAX;
            #pragma unroll
            for (int ni = 0; ni < 8; ni++) {
                int col = wn * 64 + ni * 8 + 2 * tig;
                float v0 = acc[mi][ni][half * 2 + 0];
                float v1 = acc[mi][ni][half * 2 + 1];
                if (c0 + col     >= NCLASS) v0 = -FLT_MAX;
                if (c0 + col + 1 >= NCLASS) v1 = -FLT_MAX;
                lv[ni * 2]     = v0;
                lv[ni * 2 + 1] = v1;
                mx = fmaxf(mx, fmaxf(v0, v1));
            }
            float ss = 0.f;
            #pragma unroll
            for (int j = 0; j < 16; j++) ss += __expf(lv[j] - mx);
            #pragma unroll
            for (int d = 1; d <= 2; d <<= 1) {
                float om = __shfl_xor_sync(0xffffffffu, mx, d);
                float os = __shfl_xor_sync(0xffffffffu, ss, d);
                float nm = fmaxf(mx, om);
                ss = ss * __expf(mx - nm) + os * __expf(om - nm);
                mx = nm;
            }
            if (tig == 0) {
                sm_pm[row * 2 + wn] = mx;
                sm_ps[row * 2 + wn] = ss;
            }
        }
    }
    __syncthreads();

    if (tid < 128) {
        float m0 = sm_pm[tid * 2], m1 = sm_pm[tid * 2 + 1];
        float s0 = sm_ps[tid * 2], s1 = sm_ps[tid * 2 + 1];
        float M = fmaxf(m0, m1);
        float S = s0 * __expf(m0 - M) + s1 * __expf(m1 - M);
        g_m[(size_t)(m_base + tid) * NTILES + blockIdx.y] = M;
        g_s[(size_t)(m_base + tid) * NTILES + blockIdx.y] = S;
    }
}

// ---------------------------------------------------------------------------
// Kernel 2: exact fp32 cosine at the label column, one warp per row.
// ---------------------------------------------------------------------------
__global__ __launch_bounds__(256) void label_cos_kernel(const float* __restrict__ emb,
                                                        const void* __restrict__ labels,
                                                        const float* __restrict__ weight) {
    int gid  = blockIdx.x * blockDim.x + threadIdx.x;
    int row  = gid >> 5;
    int lane = gid & 31;
    if (row >= B_ROWS) return;
    long long lab;
    if (g_lab_is64) lab = ((const long long*)labels)[row];
    else            lab = (long long)((const int*)labels)[row];
    if (lab < 0) lab = 0;
    if (lab >= NCLASS) lab = NCLASS - 1;
    const float* e = emb + (size_t)row * EMB_D;
    const float* w = weight + (size_t)lab * EMB_D;
    float s = 0.f;
    #pragma unroll
    for (int k = lane * 4; k < EMB_D; k += 128) {
        float4 ev = *(const float4*)&e[k];
        float4 wv = *(const float4*)&w[k];
        s += ev.x * wv.x + ev.y * wv.y + ev.z * wv.z + ev.w * wv.w;
    }
    #pragma unroll
    for (int o = 16; o > 0; o >>= 1) s += __shfl_xor_sync(0xffffffffu, s, o);
    if (lane == 0) g_cos_label[row] = s * g_inv_norm[lab] * (1.0f / SCALE_F);
}

// ---------------------------------------------------------------------------
// Kernel 3: combine tile partials + ArcFace label correction.
// ---------------------------------------------------------------------------
__global__ __launch_bounds__(256) void finalize_rows_kernel() {
    const int b   = blockIdx.x;
    const int tid = threadIdx.x;
    __shared__ float sh[256];

    float mx = -FLT_MAX;
    for (int t = tid; t < NTILES; t += 256)
        mx = fmaxf(mx, g_m[(size_t)b * NTILES + t]);
    sh[tid] = mx;
    __syncthreads();
    for (int o = 128; o > 0; o >>= 1) {
        if (tid < o) sh[tid] = fmaxf(sh[tid], sh[tid + o]);
        __syncthreads();
    }
    float M = sh[0];
    __syncthreads();

    float s = 0.f;
    for (int t = tid; t < NTILES; t += 256)
        s += g_s[(size_t)b * NTILES + t] * __expf(g_m[(size_t)b * NTILES + t] - M);
    sh[tid] = s;
    __syncthreads();
    for (int o = 128; o > 0; o >>= 1) {
        if (tid < o) sh[tid] += sh[tid + o];
        __syncthreads();
    }

    if (tid == 0) {
        float S  = sh[0];
        float cv = g_cos_label[b];
        float l_cos = SCALE_F * cv;
        float sine  = sqrtf(fmaxf(0.f, fminf(1.f, 1.f - cv * cv)));
        float phi   = cv * COS_M - sine * SIN_M;
        if (!(cv > TH_C)) phi = cv - MM_C;
        float l_phi = SCALE_F * phi;
        float Sc = S - expf(l_cos - M) + expf(l_phi - M);
        g_nll[b] = M + logf(Sc) - l_phi;
    }
}

// ---------------------------------------------------------------------------
// Kernel 4: mean -> scalar.
// ---------------------------------------------------------------------------
__global__ __launch_bounds__(256) void mean_kernel(float* __restrict__ out) {
    const int tid = threadIdx.x;
    __shared__ float sh[256];
    float s = 0.f;
    for (int i = tid; i < B_ROWS; i += 256) s += g_nll[i];
    sh[tid] = s;
    __syncthreads();
    for (int o = 128; o > 0; o >>= 1) {
        if (tid < o) sh[tid] += sh[tid + o];
        __syncthreads();
    }
    if (tid == 0) out[0] = sh[0] * (1.0f / (float)B_ROWS);
}

// ---------------------------------------------------------------------------
extern "C" void kernel_launch(void* const* d_in, const int* in_sizes, int n_in,
                              void* d_out, int out_size) {
    const float* emb    = (const float*)d_in[0];
    const void*  labels = d_in[1];
    const float* weight = (const float*)d_in[2];
    float*       out    = (float*)d_out;

    cudaFuncSetAttribute(gemm_lse_h, cudaFuncAttributeMaxDynamicSharedMemorySize, SMEM_DYN);

    detect_labels_kernel<<<1, 512>>>(labels);
    norm_convert_w<<<(NCLASS + 7) / 8, 256>>>(weight);
    convert_e<<<B_ROWS * EMB_D / 4 / 256, 256>>>(emb);

    dim3 grid(MBLK, NTILES);
    gemm_lse_h<<<grid, 256, SMEM_DYN>>>();

    label_cos_kernel<<<B_ROWS / 8, 256>>>(emb, labels, weight);
    finalize_rows_kernel<<<B_ROWS, 256>>>();
    mean_kernel<<<1, 256>>>(out);
}